// round 7
// baseline (speedup 1.0000x reference)
#include <cuda_runtime.h>
#include <cuda_bf16.h>
#include <cstdint>

#define N 4096
#define D 128
#define TWO_N 8192
#define KCHUNKS 32      // 4096 / 128  (128 K-values = 128 bytes per int8 row)
#define MTILES  32      // 4096 / 128

// ---------------- device-global scratch (no allocations allowed) ----------------
// int8 tiles: 16KB tile = 128 rows x 128 bytes (128 int8 K-values), SW128-swizzled.
__device__ __align__(16) uint4 g_Apack[(size_t)KCHUNKS * MTILES * 1024]; // 16 MB
__device__ __align__(16) uint4 g_CtHi[(size_t)KCHUNKS * 2 * 1024];       // 1 MB
__device__ __align__(16) uint4 g_CtLo[(size_t)KCHUNKS * 2 * 1024];       // 1 MB
__device__ __align__(16) float g_dinv[N];
__device__ __align__(16) float g_G[TWO_N * D];
__device__ __align__(16) float g_H[TWO_N * D];
__device__ __align__(16) float g_part[256 * 256];
__device__ __align__(16) float g_scale[D];
__device__ __align__(16) float g_shift[D];
__device__ float g_maxx = 0.f;     // max |x|        (atomicMax idempotent across replays)
__device__ float g_maxd = 0.f;     // max dinv
__device__ float g_s  = 0.f;       // quant scale (hi digit)
__device__ float g_s2 = 0.f;       // quant scale (lo digit) = s/254

// ---------------- helpers ----------------
__device__ __forceinline__ uint32_t smem_u32(const void* p) {
    uint32_t a;
    asm("{ .reg .u64 t; cvta.to.shared.u64 t, %1; cvt.u32.u64 %0, t; }" : "=r"(a) : "l"(p));
    return a;
}
__device__ __forceinline__ void cp16(uint32_t dst, const void* src) {
    asm volatile("cp.async.cg.shared.global [%0], [%1], 16;" :: "r"(dst), "l"(src));
}
__device__ __forceinline__ void ldmatrix_x4(uint32_t& r0, uint32_t& r1, uint32_t& r2,
                                            uint32_t& r3, uint32_t addr) {
    asm volatile("ldmatrix.sync.aligned.m8n8.x4.shared.b16 {%0,%1,%2,%3}, [%4];"
                 : "=r"(r0), "=r"(r1), "=r"(r2), "=r"(r3) : "r"(addr));
}
__device__ __forceinline__ void mma_s8(int& d0, int& d1, int& d2, int& d3,
                                       uint32_t a0, uint32_t a1, uint32_t a2, uint32_t a3,
                                       uint32_t b0, uint32_t b1) {
    asm volatile(
        "mma.sync.aligned.m16n8k32.row.col.s32.s8.s8.s32 "
        "{%0,%1,%2,%3}, {%4,%5,%6,%7}, {%8,%9}, {%0,%1,%2,%3};"
        : "+r"(d0), "+r"(d1), "+r"(d2), "+r"(d3)
        : "r"(a0), "r"(a1), "r"(a2), "r"(a3), "r"(b0), "r"(b1));
}
__device__ __forceinline__ uint8_t q8(int v) { return (uint8_t)(int8_t)v; }

// ---------------- K0: max|x| reduction ----------------
__global__ void k_scalex(const float* __restrict__ x) {
    const int idx = blockIdx.x * blockDim.x + threadIdx.x;   // 65536 threads
    const float4* x4 = (const float4*)x;
    float mx = 0.f;
    #pragma unroll
    for (int i = 0; i < 8; i++) {
        float4 v = x4[idx + i * 65536];
        mx = fmaxf(mx, fmaxf(fmaxf(fabsf(v.x), fabsf(v.y)), fmaxf(fabsf(v.z), fabsf(v.w))));
    }
    #pragma unroll
    for (int off = 16; off; off >>= 1)
        mx = fmaxf(mx, __shfl_down_sync(0xffffffffu, mx, off));
    if ((threadIdx.x & 31) == 0)
        atomicMax((int*)&g_maxx, __float_as_int(mx));   // positive floats: int order ok
}

// ---------------- K1: binarize A (int8) + degree + pack tiles (one block per row) ---
__global__ void __launch_bounds__(256) k_binpack(const float* __restrict__ aff) {
    __shared__ float ws[8];
    const int m = blockIdx.x;
    const int t = threadIdx.x;
    const float4* src = (const float4*)(aff + (size_t)m * N) + t * 4;

    uint32_t w[4];
    float cnt = 0.f;
    #pragma unroll
    for (int i = 0; i < 4; i++) {
        float4 v = src[i];
        uint32_t b0 = v.x > 0.f ? 1u : 0u; cnt += (float)b0;
        uint32_t b1 = v.y > 0.f ? 1u : 0u; cnt += (float)b1;
        uint32_t b2 = v.z > 0.f ? 1u : 0u; cnt += (float)b2;
        uint32_t b3 = v.w > 0.f ? 1u : 0u; cnt += (float)b3;
        w[i] = b0 | (b1 << 8) | (b2 << 16) | (b3 << 24);
    }
    const int kc = t >> 3;           // k-chunk 0..31 (128 bytes each)
    const int ml = m & 127;
    const size_t tb = ((size_t)kc * MTILES + (m >> 7)) * 1024;   // uint4 units
    int b = ml * 128 + (t & 7) * 16;
    g_Apack[tb + ((uint32_t)(b ^ ((b >> 3) & 0x70)) >> 4)] = make_uint4(w[0], w[1], w[2], w[3]);

    #pragma unroll
    for (int off = 16; off; off >>= 1) cnt += __shfl_down_sync(0xffffffffu, cnt, off);
    if ((t & 31) == 0) ws[t >> 5] = cnt;
    __syncthreads();
    if (t == 0) {
        float s = 0.f;
        #pragma unroll
        for (int i = 0; i < 8; i++) s += ws[i];
        float dv = rsqrtf(s + 1.0f);     // +1 from identity block
        g_dinv[m] = dv;
        atomicMax((int*)&g_maxd, __float_as_int(dv));
    }
}

// ---------------- K1b: finalize quant scale ----------------
__global__ void k_sfin() {
    float s = g_maxd * g_maxx * 1.000002f / 127.0f;
    g_s  = s;
    g_s2 = s / 254.0f;
}

// ---------------- K2: build Ct (transposed, dinv-scaled, int8 hi/lo, packed) -------
// grid (32, 2): kc = 128-K chunk, nt = x half. smem: xs[128][132] fp32 + dv[128].
#define SMEM_CT ((128 * 132 + 128) * 4)
__global__ void __launch_bounds__(256) k_buildCt(const float* __restrict__ x) {
    extern __shared__ __align__(16) float sm_ct[];
    float* xs = sm_ct;                  // [128][132]
    float* dv = sm_ct + 128 * 132;      // [128]
    const int kc = blockIdx.x;     // 0..31
    const int nt = blockIdx.y;     // 0..1
    const int t  = threadIdx.x;
    const int base_row = nt ? (N + kc * 128) : (kc * 128);
    const float4* x4 = (const float4*)x;
    #pragma unroll
    for (int i = 0; i < 16; i++) {
        int f = t + i * 256;
        int k = f >> 5, c4 = f & 31;
        *(float4*)&xs[k * 132 + c4 * 4] = x4[(size_t)(base_row + k) * 32 + c4];
    }
    if (t < 128) dv[t] = g_dinv[kc * 128 + t];
    __syncthreads();

    const float s    = g_s;
    const float rs   = 1.0f / s;
    const float rs2  = 254.0f * rs;
    const size_t tb  = ((size_t)kc * 2 + nt) * 1024;
    #pragma unroll
    for (int i = 0; i < 4; i++) {
        int u = t + i * 256;           // 1024 units: (n, 16-byte k block)
        int n = u >> 3, k16 = (u & 7) * 16;
        uint32_t hw[4], lw[4];
        #pragma unroll
        for (int q = 0; q < 4; q++) {
            uint32_t hword = 0, lword = 0;
            #pragma unroll
            for (int j = 0; j < 4; j++) {
                int k = k16 + q * 4 + j;
                float C = dv[k] * xs[k * 132 + n];
                int h = __float2int_rn(C * rs);
                float r = fmaf((float)-h, s, C);
                int l = __float2int_rn(r * rs2);
                l = max(-127, min(127, l));
                hword |= (uint32_t)q8(h) << (j * 8);
                lword |= (uint32_t)q8(l) << (j * 8);
            }
            hw[q] = hword; lw[q] = lword;
        }
        int b  = n * 128 + k16;
        int du = (b ^ ((b >> 3) & 0x70)) >> 4;
        g_CtHi[tb + du] = make_uint4(hw[0], hw[1], hw[2], hw[3]);
        g_CtLo[tb + du] = make_uint4(lw[0], lw[1], lw[2], lw[3]);
    }
}

// ---------------- K3: IMMA main GEMM + fused epilogue -> g_G ----------------
// CTA tile M=128, N=64. grid (32, 4). 8 warps = 4(m) x 2(n), warp = 32x32.
// 2-stage cp.async ring: stage = A 16KB + Bhi 8KB + Blo 8KB = 32KB.
#define STAGE_BYTES 32768
#define SMEM_MMA (2 * STAGE_BYTES)

__global__ void __launch_bounds__(256) k_mma(const float* __restrict__ x) {
    extern __shared__ __align__(1024) char smem[];
    const uint32_t sb = smem_u32(smem);
    const int tid = threadIdx.x, wid = tid >> 5, l = tid & 31;
    const int mt = blockIdx.x;          // 0..31
    const int nt = blockIdx.y;          // 0..3
    const int nth = nt >> 1;            // which Ct tile (x half)
    const int nq  = nt & 1;             // which 64-row slice of that tile
    const int warp_m = wid >> 1, warp_n = wid & 1;

    // ---- ldmatrix lane-address constants (byte offsets in 128B rows) ----
    // A x4: lanes 0-7 rows+0..7 @k, 8-15 rows+8..15 @k, 16-23 rows+0..7 @k+16, 24-31 rows+8..15 @k+16
    const int arow_l = (l & 7) + 8 * ((l >> 3) & 1);
    const int a_kx   = (l >> 4) * 16;
    int a_base[2], a_xor[2];
    #pragma unroll
    for (int mm = 0; mm < 2; mm++) {
        int row = warp_m * 32 + mm * 16 + arow_l;
        a_base[mm] = row * 128;
        a_xor[mm]  = (row & 7) << 4;
    }
    // B x4: lanes 0-7 n+0..7 @k, 8-15 n+0..7 @k+16, 16-23 n+8..15 @k, 24-31 n+8..15 @k+16
    const int brow_l = (l & 7) + 8 * (l >> 4);
    const int b_kx   = ((l >> 3) & 1) * 16;
    int b_base[2], b_xor[2];
    #pragma unroll
    for (int g = 0; g < 2; g++) {
        int row = warp_n * 32 + g * 16 + brow_l;
        b_base[g] = row * 128;
        b_xor[g]  = (row & 7) << 4;
    }

    int accH[2][4][4], accL[2][4][4];
    #pragma unroll
    for (int mm = 0; mm < 2; mm++)
        #pragma unroll
        for (int t4 = 0; t4 < 4; t4++)
            #pragma unroll
            for (int r = 0; r < 4; r++) { accH[mm][t4][r] = 0; accL[mm][t4][r] = 0; }

    const uint4* srcA = g_Apack + (size_t)mt * 1024;
    const uint4* srcH = g_CtHi  + ((size_t)nth) * 1024 + nq * 512;
    const uint4* srcL = g_CtLo  + ((size_t)nth) * 1024 + nq * 512;

    auto load_chunk = [&](int c, int s) {
        const uint32_t base = sb + s * STAGE_BYTES;
        const uint4* a  = srcA + (size_t)c * MTILES * 1024;
        const uint4* bh = srcH + (size_t)c * 2 * 1024;
        const uint4* bl = srcL + (size_t)c * 2 * 1024;
        #pragma unroll
        for (int i = 0; i < 4; i++)
            cp16(base + (tid + i * 256) * 16, a + tid + i * 256);
        #pragma unroll
        for (int i = 0; i < 2; i++)
            cp16(base + 16384 + (tid + i * 256) * 16, bh + tid + i * 256);
        #pragma unroll
        for (int i = 0; i < 2; i++)
            cp16(base + 24576 + (tid + i * 256) * 16, bl + tid + i * 256);
        asm volatile("cp.async.commit_group;" ::: "memory");
    };

    load_chunk(0, 0);
    for (int c = 0; c < KCHUNKS; c++) {
        const int s = c & 1;
        if (c < KCHUNKS - 1) {
            load_chunk(c + 1, s ^ 1);
            asm volatile("cp.async.wait_group 1;" ::: "memory");
        } else {
            asm volatile("cp.async.wait_group 0;" ::: "memory");
        }
        __syncthreads();

        const uint32_t Ab = sb + s * STAGE_BYTES;
        const uint32_t Bh = Ab + 16384;
        const uint32_t Bl = Ab + 24576;
        #pragma unroll
        for (int ks = 0; ks < 4; ks++) {
            const int k2 = ks * 32;                 // byte offset of this k32 step
            uint32_t a[2][4], bh[2][4], bl[2][4];
            #pragma unroll
            for (int mm = 0; mm < 2; mm++)
                ldmatrix_x4(a[mm][0], a[mm][1], a[mm][2], a[mm][3],
                            Ab + a_base[mm] + ((k2 + a_kx) ^ a_xor[mm]));
            #pragma unroll
            for (int g = 0; g < 2; g++) {
                uint32_t off = b_base[g] + ((k2 + b_kx) ^ b_xor[g]);
                ldmatrix_x4(bh[g][0], bh[g][1], bh[g][2], bh[g][3], Bh + off);
                ldmatrix_x4(bl[g][0], bl[g][1], bl[g][2], bl[g][3], Bl + off);
            }
            // bh[g]: regs {0,1} = n8-group (2g) k/k+16, {2,3} = n8-group (2g+1)
            #pragma unroll
            for (int mm = 0; mm < 2; mm++)
                #pragma unroll
                for (int t4 = 0; t4 < 4; t4++) {
                    const int g = t4 >> 1, o = (t4 & 1) * 2;
                    mma_s8(accH[mm][t4][0], accH[mm][t4][1], accH[mm][t4][2], accH[mm][t4][3],
                           a[mm][0], a[mm][1], a[mm][2], a[mm][3], bh[g][o], bh[g][o + 1]);
                    mma_s8(accL[mm][t4][0], accL[mm][t4][1], accL[mm][t4][2], accL[mm][t4][3],
                           a[mm][0], a[mm][1], a[mm][2], a[mm][3], bl[g][o], bl[g][o + 1]);
                }
        }
        __syncthreads();
    }

    // ---- epilogue: G = dinv * (s*Phi + s2*Plo) + dinv^2 * x_skip ----
    const float s1 = g_s, s2 = g_s2;
    const int colhalf = nth;
    const int dcol0   = nq * 64 + warp_n * 32;
    #pragma unroll
    for (int mm = 0; mm < 2; mm++) {
        const int i0 = mt * 128 + warp_m * 32 + mm * 16 + (l >> 2);
        #pragma unroll
        for (int rp = 0; rp < 2; rp++) {
            const int i  = i0 + rp * 8;
            const float di  = g_dinv[i];
            const float di2 = di * di;
            const int gr = colhalf ? (N + i) : i;
            const int xr = colhalf ? i : (N + i);
            #pragma unroll
            for (int t4 = 0; t4 < 4; t4++) {
                const int cc = dcol0 + t4 * 8 + (l & 3) * 2;
                float2 xv = *(const float2*)(x + (size_t)xr * D + cc);
                float p0 = s1 * (float)accH[mm][t4][rp * 2 + 0] + s2 * (float)accL[mm][t4][rp * 2 + 0];
                float p1 = s1 * (float)accH[mm][t4][rp * 2 + 1] + s2 * (float)accL[mm][t4][rp * 2 + 1];
                float2 o;
                o.x = di * p0 + di2 * xv.x;
                o.y = di * p1 + di2 * xv.y;
                *(float2*)(g_G + (size_t)gr * D + cc) = o;
            }
        }
    }
}

// ---------------- K4: H = G @ W + per-block BN partials (R5 version) ----------------
__global__ void __launch_bounds__(256) k_gemm2(const float* __restrict__ W) {
    __shared__ float Gs[32][128];
    __shared__ float Ws[32][128];
    __shared__ float ssum[128], ssq[128];

    const int tid  = threadIdx.x;
    const int row0 = blockIdx.x * 32;
    const float4* Gsrc = (const float4*)(g_G + (size_t)row0 * D);
    #pragma unroll
    for (int it = 0; it < 4; it++) ((float4*)Gs)[tid + it * 256] = Gsrc[tid + it * 256];
    if (tid < 128) { ssum[tid] = 0.f; ssq[tid] = 0.f; }

    const int rg = tid >> 5;
    const int cg = tid & 31;
    float acc[4][4];
    #pragma unroll
    for (int m = 0; m < 4; m++)
        #pragma unroll
        for (int j = 0; j < 4; j++) acc[m][j] = 0.f;

    for (int kc = 0; kc < D; kc += 32) {
        __syncthreads();
        #pragma unroll
        for (int it = 0; it < 4; it++) {
            int f4 = tid + it * 256;
            int kk = f4 >> 5;
            int c4 = f4 & 31;
            ((float4*)Ws)[f4] = *(const float4*)(W + (size_t)(kc + kk) * D + c4 * 4);
        }
        __syncthreads();
        #pragma unroll
        for (int kk = 0; kk < 32; kk++) {
            float4 wv = *(float4*)&Ws[kk][cg * 4];
            float a0 = Gs[rg * 4 + 0][kc + kk];
            float a1 = Gs[rg * 4 + 1][kc + kk];
            float a2 = Gs[rg * 4 + 2][kc + kk];
            float a3 = Gs[rg * 4 + 3][kc + kk];
            acc[0][0] += a0 * wv.x; acc[0][1] += a0 * wv.y; acc[0][2] += a0 * wv.z; acc[0][3] += a0 * wv.w;
            acc[1][0] += a1 * wv.x; acc[1][1] += a1 * wv.y; acc[1][2] += a1 * wv.z; acc[1][3] += a1 * wv.w;
            acc[2][0] += a2 * wv.x; acc[2][1] += a2 * wv.y; acc[2][2] += a2 * wv.z; acc[2][3] += a2 * wv.w;
            acc[3][0] += a3 * wv.x; acc[3][1] += a3 * wv.y; acc[3][2] += a3 * wv.z; acc[3][3] += a3 * wv.w;
        }
    }

    #pragma unroll
    for (int m = 0; m < 4; m++) {
        int r = row0 + rg * 4 + m;
        float4 hv;
        hv.x = acc[m][0]; hv.y = acc[m][1]; hv.z = acc[m][2]; hv.w = acc[m][3];
        *(float4*)(g_H + (size_t)r * D + cg * 4) = hv;
        atomicAdd(&ssum[cg * 4 + 0], hv.x); atomicAdd(&ssq[cg * 4 + 0], hv.x * hv.x);
        atomicAdd(&ssum[cg * 4 + 1], hv.y); atomicAdd(&ssq[cg * 4 + 1], hv.y * hv.y);
        atomicAdd(&ssum[cg * 4 + 2], hv.z); atomicAdd(&ssq[cg * 4 + 2], hv.z * hv.z);
        atomicAdd(&ssum[cg * 4 + 3], hv.w); atomicAdd(&ssq[cg * 4 + 3], hv.w * hv.w);
    }
    __syncthreads();
    if (tid < 128) {
        g_part[blockIdx.x * 256 + tid]       = ssum[tid];
        g_part[blockIdx.x * 256 + 128 + tid] = ssq[tid];
    }
}

// ---------------- K5: BN stats ----------------
__global__ void k_stats(const float* __restrict__ gamma, const float* __restrict__ beta) {
    int c = threadIdx.x;
    float s = 0.f, q = 0.f;
    for (int b = 0; b < 256; b++) {
        s += g_part[b * 256 + c];
        q += g_part[b * 256 + 128 + c];
    }
    const float inv = 1.f / (float)TWO_N;
    float mean = s * inv;
    float var  = q * inv - mean * mean;
    float sc   = gamma[c] * rsqrtf(var + 1e-5f);
    g_scale[c] = sc;
    g_shift[c] = beta[c] - mean * sc;
}

// ---------------- K6: out = relu(H * scale + shift) ----------------
__global__ void k_final(float* __restrict__ out) {
    int idx = blockIdx.x * blockDim.x + threadIdx.x;
    int c4  = idx & 31;
    float4 h = ((const float4*)g_H)[idx];
    float4 r;
    r.x = fmaxf(h.x * g_scale[c4 * 4 + 0] + g_shift[c4 * 4 + 0], 0.f);
    r.y = fmaxf(h.y * g_scale[c4 * 4 + 1] + g_shift[c4 * 4 + 1], 0.f);
    r.z = fmaxf(h.z * g_scale[c4 * 4 + 2] + g_shift[c4 * 4 + 2], 0.f);
    r.w = fmaxf(h.w * g_scale[c4 * 4 + 3] + g_shift[c4 * 4 + 3], 0.f);
    ((float4*)out)[idx] = r;
}

// ---------------- launch ----------------
extern "C" void kernel_launch(void* const* d_in, const int* in_sizes, int n_in,
                              void* d_out, int out_size) {
    const float *x = nullptr, *aff = nullptr, *W = nullptr, *gamma = nullptr, *beta = nullptr;
    for (int i = 0; i < n_in; i++) {
        int sz = in_sizes[i];
        if      (sz == TWO_N * D)  x   = (const float*)d_in[i];
        else if (sz == N * N)      aff = (const float*)d_in[i];
        else if (sz == D * D)      W   = (const float*)d_in[i];
        else if (sz == D) {
            if (!gamma) gamma = (const float*)d_in[i];
            else        beta  = (const float*)d_in[i];
        }
    }
    float* out = (float*)d_out;

    cudaFuncSetAttribute(k_mma,     cudaFuncAttributeMaxDynamicSharedMemorySize, SMEM_MMA);
    cudaFuncSetAttribute(k_buildCt, cudaFuncAttributeMaxDynamicSharedMemorySize, SMEM_CT);

    k_scalex <<<256, 256>>>(x);
    k_binpack<<<4096, 256>>>(aff);
    k_sfin   <<<1, 1>>>();
    dim3 gc(KCHUNKS, 2);
    k_buildCt<<<gc, 256, SMEM_CT>>>(x);
    dim3 gm(MTILES, 4);
    k_mma    <<<gm, 256, SMEM_MMA>>>(x);
    k_gemm2  <<<256, 256>>>(W);
    k_stats  <<<1, 128>>>(gamma, beta);
    k_final  <<<1024, 256>>>(out);
}

// round 11
// speedup vs baseline: 2.1821x; 2.1821x over previous
#include <cuda_runtime.h>
#include <cuda_fp16.h>
#include <cstdint>

#define N 4096
#define D 128
#define TWO_N 8192
#define KCHUNKS 64      // 4096 / 64  (64 fp16 K-values = 128 bytes per row)
#define MTILES  32      // 4096 / 128

// ---------------- device-global scratch (no allocations allowed) ----------------
// Packed tiles: 16KB tile = 128 rows x 128 bytes (64 fp16 K-values), SW128-swizzled.
__device__ __align__(16) uint4 g_Apack[(size_t)KCHUNKS * MTILES * 1024]; // 32 MB
__device__ __align__(16) uint4 g_Ct[(size_t)KCHUNKS * 2 * 1024];         // 2 MB
__device__ __align__(16) float g_dinv[N];
__device__ __align__(16) float g_G[TWO_N * D];
__device__ __align__(16) float g_H[TWO_N * D];
__device__ __align__(16) float g_part[256 * 256];
__device__ __align__(16) float g_scale[D];
__device__ __align__(16) float g_shift[D];

// ---------------- helpers ----------------
__device__ __forceinline__ uint32_t smem_u32(const void* p) {
    uint32_t a;
    asm("{ .reg .u64 t; cvta.to.shared.u64 t, %1; cvt.u32.u64 %0, t; }" : "=r"(a) : "l"(p));
    return a;
}
__device__ __forceinline__ void cp16(uint32_t dst, const void* src) {
    asm volatile("cp.async.cg.shared.global [%0], [%1], 16;" :: "r"(dst), "l"(src));
}
__device__ __forceinline__ void ldmatrix_x4(uint32_t& r0, uint32_t& r1, uint32_t& r2,
                                            uint32_t& r3, uint32_t addr) {
    asm volatile("ldmatrix.sync.aligned.m8n8.x4.shared.b16 {%0,%1,%2,%3}, [%4];"
                 : "=r"(r0), "=r"(r1), "=r"(r2), "=r"(r3) : "r"(addr));
}
__device__ __forceinline__ void mma_f16(float& d0, float& d1, float& d2, float& d3,
                                        uint32_t a0, uint32_t a1, uint32_t a2, uint32_t a3,
                                        uint32_t b0, uint32_t b1) {
    asm volatile(
        "mma.sync.aligned.m16n8k16.row.col.f32.f16.f16.f32 "
        "{%0,%1,%2,%3}, {%4,%5,%6,%7}, {%8,%9}, {%0,%1,%2,%3};"
        : "+f"(d0), "+f"(d1), "+f"(d2), "+f"(d3)
        : "r"(a0), "r"(a1), "r"(a2), "r"(a3), "r"(b0), "r"(b1));
}

// ---------------- K1: binarize A (fp16 {0,1}) + degree + pack tiles ----------------
__global__ void __launch_bounds__(256) k_binpack(const float* __restrict__ aff) {
    __shared__ float ws[8];
    const int m = blockIdx.x;
    const int t = threadIdx.x;
    const float4* src = (const float4*)(aff + (size_t)m * N) + t * 4;

    unsigned short h[16];
    float cnt = 0.f;
    #pragma unroll
    for (int i = 0; i < 4; i++) {
        float4 v = src[i];
        h[i*4+0] = v.x > 0.f ? (unsigned short)0x3C00 : 0; cnt += (v.x > 0.f);
        h[i*4+1] = v.y > 0.f ? (unsigned short)0x3C00 : 0; cnt += (v.y > 0.f);
        h[i*4+2] = v.z > 0.f ? (unsigned short)0x3C00 : 0; cnt += (v.z > 0.f);
        h[i*4+3] = v.w > 0.f ? (unsigned short)0x3C00 : 0; cnt += (v.w > 0.f);
    }
    uint32_t w[8];
    #pragma unroll
    for (int j = 0; j < 8; j++) w[j] = (uint32_t)h[2*j] | ((uint32_t)h[2*j+1] << 16);

    const int kc = t >> 2;           // k-chunk 0..63 handled by this thread
    const int ml = m & 127;
    const size_t tb = ((size_t)kc * MTILES + (m >> 7)) * 1024;   // uint4 units
    int b0 = ml * 128 + (t & 3) * 32;
    int b1 = b0 + 16;
    g_Apack[tb + ((uint32_t)(b0 ^ ((b0 >> 3) & 0x70)) >> 4)] = make_uint4(w[0], w[1], w[2], w[3]);
    g_Apack[tb + ((uint32_t)(b1 ^ ((b1 >> 3) & 0x70)) >> 4)] = make_uint4(w[4], w[5], w[6], w[7]);

    #pragma unroll
    for (int off = 16; off; off >>= 1) cnt += __shfl_down_sync(0xffffffffu, cnt, off);
    if ((t & 31) == 0) ws[t >> 5] = cnt;
    __syncthreads();
    if (t == 0) {
        float s = 0.f;
        #pragma unroll
        for (int i = 0; i < 8; i++) s += ws[i];
        g_dinv[m] = rsqrtf(s + 1.0f);
    }
}

// ---------------- K2: build Ct (transposed, dinv-scaled, fp16, packed) -------------
__global__ void __launch_bounds__(256) k_buildCt(const float* __restrict__ x) {
    __shared__ float xs[64][129];
    __shared__ float dv[64];
    const int kc = blockIdx.x;     // 0..63
    const int nt = blockIdx.y;     // 0..1 (top/bottom half of x)
    const int t  = threadIdx.x;
    const int base_row = nt ? (N + kc * 64) : (kc * 64);
    const float4* x4 = (const float4*)x;
    #pragma unroll
    for (int i = 0; i < 8; i++) {
        int f = t + i * 256;
        int k = f >> 5, c4 = f & 31;
        float4 v = x4[(size_t)(base_row + k) * 32 + c4];
        xs[k][c4*4+0] = v.x; xs[k][c4*4+1] = v.y; xs[k][c4*4+2] = v.z; xs[k][c4*4+3] = v.w;
    }
    if (t < 64) dv[t] = g_dinv[kc * 64 + t];
    __syncthreads();

    const size_t tb = ((size_t)kc * 2 + nt) * 1024;
    #pragma unroll
    for (int i = 0; i < 4; i++) {
        int u = t + i * 256;
        int n = u >> 3, k8 = (u & 7) * 8;
        uint32_t hw[4];
        #pragma unroll
        for (int j = 0; j < 4; j++) {
            float v0 = dv[k8 + 2*j]     * xs[k8 + 2*j][n];
            float v1 = dv[k8 + 2*j + 1] * xs[k8 + 2*j + 1][n];
            __half h0 = __float2half_rn(v0);
            __half h1 = __float2half_rn(v1);
            hw[j] = (uint32_t)__half_as_ushort(h0) | ((uint32_t)__half_as_ushort(h1) << 16);
        }
        int b  = n * 128 + k8 * 2;
        int du = (b ^ ((b >> 3) & 0x70)) >> 4;
        g_Ct[tb + du] = make_uint4(hw[0], hw[1], hw[2], hw[3]);
    }
}

// ---------------- K3: HMMA fp16 main GEMM + fused epilogue -> g_G ----------------
// CTA tile M=128, N=64. grid (32, 4). 8 warps = 4(m) x 2(n), warp = 32x32.
// 2-stage cp.async ring: stage = A 16KB + B 8KB = 24KB.
#define STAGE_BYTES 24576
#define SMEM_MMA (2 * STAGE_BYTES)

__global__ void __launch_bounds__(256) k_mma(const float* __restrict__ x) {
    extern __shared__ __align__(1024) char smem[];
    const uint32_t sb = smem_u32(smem);
    const int tid = threadIdx.x, wid = tid >> 5, l = tid & 31;
    const int mt = blockIdx.x;          // 0..31
    const int nt = blockIdx.y;          // 0..3
    const int nth = nt >> 1;            // which Ct tile (x half)
    const int nq  = nt & 1;             // which 64-row slice of that tile
    const int warp_m = wid >> 1, warp_n = wid & 1;

    // ---- per-lane ldmatrix address constants (tile-relative) ----
    const int arow_l = (l & 7) + 8 * ((l >> 3) & 1);
    const int a_kx   = (l >> 4) * 16;
    int a_base[2], a_xor[2];
    #pragma unroll
    for (int mm = 0; mm < 2; mm++) {
        int row = warp_m * 32 + mm * 16 + arow_l;
        a_base[mm] = row * 128;
        a_xor[mm]  = (row & 7) << 4;
    }
    const int brow_l = (l & 7) + 8 * (l >> 4);
    const int b_kx   = ((l >> 3) & 1) * 16;
    int b_base[2], b_xor[2];
    #pragma unroll
    for (int g = 0; g < 2; g++) {
        int row = warp_n * 32 + g * 16 + brow_l;
        b_base[g] = row * 128;
        b_xor[g]  = (row & 7) << 4;
    }

    float acc[2][4][4];
    #pragma unroll
    for (int mm = 0; mm < 2; mm++)
        #pragma unroll
        for (int t4 = 0; t4 < 4; t4++)
            #pragma unroll
            for (int r = 0; r < 4; r++) acc[mm][t4][r] = 0.f;

    const uint4* srcA = g_Apack + (size_t)mt * 1024;
    const uint4* srcB = g_Ct    + ((size_t)nth) * 1024 + nq * 512;

    auto load_chunk = [&](int c, int s) {
        const uint32_t base = sb + s * STAGE_BYTES;
        const uint4* a = srcA + (size_t)c * MTILES * 1024;
        const uint4* b = srcB + (size_t)c * 2 * 1024;
        #pragma unroll
        for (int i = 0; i < 4; i++)
            cp16(base + (tid + i * 256) * 16, a + tid + i * 256);
        #pragma unroll
        for (int i = 0; i < 2; i++)
            cp16(base + 16384 + (tid + i * 256) * 16, b + tid + i * 256);
        asm volatile("cp.async.commit_group;" ::: "memory");
    };

    load_chunk(0, 0);
    for (int c = 0; c < KCHUNKS; c++) {
        const int s = c & 1;
        if (c < KCHUNKS - 1) {
            load_chunk(c + 1, s ^ 1);
            asm volatile("cp.async.wait_group 1;" ::: "memory");
        } else {
            asm volatile("cp.async.wait_group 0;" ::: "memory");
        }
        __syncthreads();

        const uint32_t Ab = sb + s * STAGE_BYTES;
        const uint32_t Bb = Ab + 16384;
        #pragma unroll
        for (int ks = 0; ks < 4; ks++) {
            const int k2 = ks * 32;
            uint32_t a[2][4], bv[2][4];
            #pragma unroll
            for (int mm = 0; mm < 2; mm++)
                ldmatrix_x4(a[mm][0], a[mm][1], a[mm][2], a[mm][3],
                            Ab + a_base[mm] + ((k2 + a_kx) ^ a_xor[mm]));
            #pragma unroll
            for (int g = 0; g < 2; g++)
                ldmatrix_x4(bv[g][0], bv[g][1], bv[g][2], bv[g][3],
                            Bb + b_base[g] + ((k2 + b_kx) ^ b_xor[g]));
            #pragma unroll
            for (int mm = 0; mm < 2; mm++)
                #pragma unroll
                for (int t4 = 0; t4 < 4; t4++) {
                    const int g = t4 >> 1, o = (t4 & 1) * 2;
                    mma_f16(acc[mm][t4][0], acc[mm][t4][1], acc[mm][t4][2], acc[mm][t4][3],
                            a[mm][0], a[mm][1], a[mm][2], a[mm][3], bv[g][o], bv[g][o + 1]);
                }
        }
        __syncthreads();
    }

    // ---- epilogue: G = dinv * P + dinv^2 * x_skip ----
    const int colhalf = nth;
    const int dcol0   = nq * 64 + warp_n * 32;
    #pragma unroll
    for (int mm = 0; mm < 2; mm++) {
        const int i0 = mt * 128 + warp_m * 32 + mm * 16 + (l >> 2);
        #pragma unroll
        for (int rp = 0; rp < 2; rp++) {
            const int i  = i0 + rp * 8;
            const float di  = g_dinv[i];
            const float di2 = di * di;
            const int gr = colhalf ? (N + i) : i;
            const int xr = colhalf ? i : (N + i);
            #pragma unroll
            for (int t4 = 0; t4 < 4; t4++) {
                const int cc = dcol0 + t4 * 8 + (l & 3) * 2;
                float2 xv = *(const float2*)(x + (size_t)xr * D + cc);
                float2 o;
                o.x = di * acc[mm][t4][rp * 2 + 0] + di2 * xv.x;
                o.y = di * acc[mm][t4][rp * 2 + 1] + di2 * xv.y;
                *(float2*)(g_G + (size_t)gr * D + cc) = o;
            }
        }
    }
}

// ---------------- K4: H = G @ W + per-block BN partials (R5 version) ----------------
__global__ void __launch_bounds__(256) k_gemm2(const float* __restrict__ W) {
    __shared__ float Gs[32][128];
    __shared__ float Ws[32][128];
    __shared__ float ssum[128], ssq[128];

    const int tid  = threadIdx.x;
    const int row0 = blockIdx.x * 32;
    const float4* Gsrc = (const float4*)(g_G + (size_t)row0 * D);
    #pragma unroll
    for (int it = 0; it < 4; it++) ((float4*)Gs)[tid + it * 256] = Gsrc[tid + it * 256];
    if (tid < 128) { ssum[tid] = 0.f; ssq[tid] = 0.f; }

    const int rg = tid >> 5;
    const int cg = tid & 31;
    float acc[4][4];
    #pragma unroll
    for (int m = 0; m < 4; m++)
        #pragma unroll
        for (int j = 0; j < 4; j++) acc[m][j] = 0.f;

    for (int kc = 0; kc < D; kc += 32) {
        __syncthreads();
        #pragma unroll
        for (int it = 0; it < 4; it++) {
            int f4 = tid + it * 256;
            int kk = f4 >> 5;
            int c4 = f4 & 31;
            ((float4*)Ws)[f4] = *(const float4*)(W + (size_t)(kc + kk) * D + c4 * 4);
        }
        __syncthreads();
        #pragma unroll
        for (int kk = 0; kk < 32; kk++) {
            float4 wv = *(float4*)&Ws[kk][cg * 4];
            float a0 = Gs[rg * 4 + 0][kc + kk];
            float a1 = Gs[rg * 4 + 1][kc + kk];
            float a2 = Gs[rg * 4 + 2][kc + kk];
            float a3 = Gs[rg * 4 + 3][kc + kk];
            acc[0][0] += a0 * wv.x; acc[0][1] += a0 * wv.y; acc[0][2] += a0 * wv.z; acc[0][3] += a0 * wv.w;
            acc[1][0] += a1 * wv.x; acc[1][1] += a1 * wv.y; acc[1][2] += a1 * wv.z; acc[1][3] += a1 * wv.w;
            acc[2][0] += a2 * wv.x; acc[2][1] += a2 * wv.y; acc[2][2] += a2 * wv.z; acc[2][3] += a2 * wv.w;
            acc[3][0] += a3 * wv.x; acc[3][1] += a3 * wv.y; acc[3][2] += a3 * wv.z; acc[3][3] += a3 * wv.w;
        }
    }

    #pragma unroll
    for (int m = 0; m < 4; m++) {
        int r = row0 + rg * 4 + m;
        float4 hv;
        hv.x = acc[m][0]; hv.y = acc[m][1]; hv.z = acc[m][2]; hv.w = acc[m][3];
        *(float4*)(g_H + (size_t)r * D + cg * 4) = hv;
        atomicAdd(&ssum[cg * 4 + 0], hv.x); atomicAdd(&ssq[cg * 4 + 0], hv.x * hv.x);
        atomicAdd(&ssum[cg * 4 + 1], hv.y); atomicAdd(&ssq[cg * 4 + 1], hv.y * hv.y);
        atomicAdd(&ssum[cg * 4 + 2], hv.z); atomicAdd(&ssq[cg * 4 + 2], hv.z * hv.z);
        atomicAdd(&ssum[cg * 4 + 3], hv.w); atomicAdd(&ssq[cg * 4 + 3], hv.w * hv.w);
    }
    __syncthreads();
    if (tid < 128) {
        g_part[blockIdx.x * 256 + tid]       = ssum[tid];
        g_part[blockIdx.x * 256 + 128 + tid] = ssq[tid];
    }
}

// ---------------- K5: BN stats ----------------
__global__ void k_stats(const float* __restrict__ gamma, const float* __restrict__ beta) {
    int c = threadIdx.x;
    float s = 0.f, q = 0.f;
    for (int b = 0; b < 256; b++) {
        s += g_part[b * 256 + c];
        q += g_part[b * 256 + 128 + c];
    }
    const float inv = 1.f / (float)TWO_N;
    float mean = s * inv;
    float var  = q * inv - mean * mean;
    float sc   = gamma[c] * rsqrtf(var + 1e-5f);
    g_scale[c] = sc;
    g_shift[c] = beta[c] - mean * sc;
}

// ---------------- K6: out = relu(H * scale + shift) ----------------
__global__ void k_final(float* __restrict__ out) {
    int idx = blockIdx.x * blockDim.x + threadIdx.x;
    int c4  = idx & 31;
    float4 h = ((const float4*)g_H)[idx];
    float4 r;
    r.x = fmaxf(h.x * g_scale[c4 * 4 + 0] + g_shift[c4 * 4 + 0], 0.f);
    r.y = fmaxf(h.y * g_scale[c4 * 4 + 1] + g_shift[c4 * 4 + 1], 0.f);
    r.z = fmaxf(h.z * g_scale[c4 * 4 + 2] + g_shift[c4 * 4 + 2], 0.f);
    r.w = fmaxf(h.w * g_scale[c4 * 4 + 3] + g_shift[c4 * 4 + 3], 0.f);
    ((float4*)out)[idx] = r;
}

// ---------------- launch ----------------
extern "C" void kernel_launch(void* const* d_in, const int* in_sizes, int n_in,
                              void* d_out, int out_size) {
    const float *x = nullptr, *aff = nullptr, *W = nullptr, *gamma = nullptr, *beta = nullptr;
    for (int i = 0; i < n_in; i++) {
        int sz = in_sizes[i];
        if      (sz == TWO_N * D)  x   = (const float*)d_in[i];
        else if (sz == N * N)      aff = (const float*)d_in[i];
        else if (sz == D * D)      W   = (const float*)d_in[i];
        else if (sz == D) {
            if (!gamma) gamma = (const float*)d_in[i];
            else        beta  = (const float*)d_in[i];
        }
    }
    float* out = (float*)d_out;

    cudaFuncSetAttribute(k_mma, cudaFuncAttributeMaxDynamicSharedMemorySize, SMEM_MMA);

    k_binpack<<<4096, 256>>>(aff);
    dim3 gc(64, 2);
    k_buildCt<<<gc, 256>>>(x);
    dim3 gm(MTILES, 4);
    k_mma<<<gm, 256, SMEM_MMA>>>(x);
    k_gemm2<<<256, 256>>>(W);
    k_stats<<<1, 128>>>(gamma, beta);
    k_final<<<1024, 256>>>(out);
}